// round 15
// baseline (speedup 1.0000x reference)
#include <cuda_runtime.h>
#include <cuda_fp16.h>
#include <cstdint>
#include <mma.h>

using namespace nvcuda;

// Problem constants
#define B_  8
#define T_  2048
#define D_  1024
#define H_  1024
#define R_  128
#define M_  (B_*T_)      // 16384 rows
#define C_  16           // scan chunks
#define L_  128          // chunk length (T_/C_)

// ---------------------------------------------------------------------------
// Scratch (device globals: allocation APIs are forbidden)
// ---------------------------------------------------------------------------
__device__ __half d_u1h[D_ * R_], d_u2h[D_ * R_];
__device__ __half d_v1h[R_ * H_], d_v2h[R_ * H_];   // pre-scaled by gamma
__device__ __half d_tmph[(size_t)M_ * 2 * R_];      // 8 MB: x@U1 | x@U2 (fp16)
__device__ __half d_bxbyh[(size_t)M_ * 2 * H_];     // 64 MB (fp16)
__device__ float d_e1[B_ * C_ * H_], d_e2[B_ * C_ * H_];
__device__ float d_i1[B_ * C_ * H_], d_i2[B_ * C_ * H_];
__device__ float d_g[H_], d_phi[H_];

// ---------------------------------------------------------------------------
// Prep: decay params + U conv + V conv (gamma recomputed per V-thread).
// ---------------------------------------------------------------------------
__global__ void prep_kernel(const float* __restrict__ nu_log,
                            const float* __restrict__ theta_log,
                            const float* __restrict__ U1,
                            const float* __restrict__ U2,
                            const float* __restrict__ V1,
                            const float* __restrict__ V2) {
    int i = blockIdx.x * blockDim.x + threadIdx.x;
    if (i < H_) {
        float r = expf(-expf(nu_log[i]));
        float th = expf(theta_log[i]);
        d_g[i]   = r * cosf(th);
        d_phi[i] = r * sinf(th);
    }
    if (i < D_ * R_) {
        d_u1h[i] = __float2half_rn(U1[i]);
        d_u2h[i] = __float2half_rn(U2[i]);
    }
    if (i < R_ * H_) {
        int h = i % H_;
        float r = expf(-expf(nu_log[h]));
        float gm = sqrtf(fmaxf(1.0f - r * r, 0.0f));
        d_v1h[i] = __float2half_rn(V1[i] * gm);
        d_v2h[i] = __float2half_rn(V2[i] * gm);
    }
}

// cp.async helpers
__device__ __forceinline__ void cp_async16(void* dst, const void* src) {
    unsigned s = (unsigned)__cvta_generic_to_shared(dst);
    asm volatile("cp.async.ca.shared.global [%0], [%1], 16;" :: "r"(s), "l"(src));
}
__device__ __forceinline__ void cp_commit() { asm volatile("cp.async.commit_group;"); }
template <int N>
__device__ __forceinline__ void cp_wait() { asm volatile("cp.async.wait_group %0;" :: "n"(N)); }

// ---------------------------------------------------------------------------
// Stage 1 (fused x conversion): tmph[M,256] = fp16(x) @ [U1|U2]
// BM=128, BN=256 (x read ONCE), 512 threads = 16 warps (4m x 4n; 32x64/warp),
// KT=32, double-buffered: A prefetched fp32 -> converted -> STS; B cp.async.
// Dynamic smem: 2*(128*40 + 32*264)*2 = 54272 B.
// ---------------------------------------------------------------------------
__global__ __launch_bounds__(512, 1)
void gemm1_fused(const float* __restrict__ x,
                 const __half* __restrict__ u1h, const __half* __restrict__ u2h,
                 __half* __restrict__ tmph) {
    constexpr int ALD = 40;
    constexpr int BLD = 264;
    constexpr int ASTG = 128 * ALD;
    constexpr int BSTG = 32 * BLD;

    extern __shared__ __align__(16) __half smh[];
    __half* As = smh;                  // [2][128][40]
    __half* Bs = smh + 2 * ASTG;       // [2][32][264]

    const int tid  = threadIdx.x;
    const int warp = tid >> 5;
    const int lane = tid & 31;
    const int wm = warp >> 2;
    const int wn = warp & 3;
    const int m0 = blockIdx.x * 128;

    const int a_row = tid >> 2, a_col = (tid & 3) * 8;
    const int b_row = tid >> 4, b_col = (tid & 15) * 16;
    const __half* bsrc = (b_col < R_) ? &u1h[b_col] : &u2h[b_col - R_];

    float4 pa[2];
    auto prefA = [&](int k0) {
        const float* ap = &x[(size_t)(m0 + a_row) * D_ + k0 + a_col];
        pa[0] = *(const float4*)ap;
        pa[1] = *(const float4*)(ap + 4);
    };
    auto stageA = [&](int s) {
        __half2 h[4];
        h[0] = __floats2half2_rn(pa[0].x, pa[0].y);
        h[1] = __floats2half2_rn(pa[0].z, pa[0].w);
        h[2] = __floats2half2_rn(pa[1].x, pa[1].y);
        h[3] = __floats2half2_rn(pa[1].z, pa[1].w);
        *(uint4*)&As[s * ASTG + a_row * ALD + a_col] = *(uint4*)h;
    };
    auto cpB = [&](int s, int k0) {
        const __half* bp = bsrc + (size_t)(k0 + b_row) * R_;
        cp_async16(&Bs[s * BSTG + b_row * BLD + b_col],     bp);
        cp_async16(&Bs[s * BSTG + b_row * BLD + b_col + 8], bp + 8);
        cp_commit();
    };

    wmma::fragment<wmma::accumulator, 16, 16, 16, float> acc[2][4];
#pragma unroll
    for (int i = 0; i < 2; i++)
#pragma unroll
        for (int j = 0; j < 4; j++) wmma::fill_fragment(acc[i][j], 0.0f);

    const int nK = D_ / 32;
    prefA(0);
    cpB(0, 0);

    for (int kt = 0; kt < nK; kt++) {
        const int s = kt & 1;
        stageA(s);
        if (kt + 1 < nK) {
            prefA((kt + 1) * 32);
            cpB(1 - s, (kt + 1) * 32);
            cp_wait<1>();
        } else {
            cp_wait<0>();
        }
        __syncthreads();

#pragma unroll
        for (int ks = 0; ks < 2; ks++) {
            wmma::fragment<wmma::matrix_a, 16, 16, 16, __half, wmma::row_major> af[2];
            wmma::fragment<wmma::matrix_b, 16, 16, 16, __half, wmma::row_major> bf[4];
#pragma unroll
            for (int i = 0; i < 2; i++)
                wmma::load_matrix_sync(af[i], &As[s * ASTG + (wm * 32 + i * 16) * ALD + ks * 16], ALD);
#pragma unroll
            for (int j = 0; j < 4; j++)
                wmma::load_matrix_sync(bf[j], &Bs[s * BSTG + (ks * 16) * BLD + wn * 64 + j * 16], BLD);
#pragma unroll
            for (int i = 0; i < 2; i++)
#pragma unroll
                for (int j = 0; j < 4; j++)
                    wmma::mma_sync(acc[i][j], af[i], bf[j], acc[i][j]);
        }
        __syncthreads();
    }

    float* wbuf = (float*)smh + warp * 256;
    const int lr = lane >> 1;
    const int lc = (lane & 1) * 8;
#pragma unroll
    for (int i = 0; i < 2; i++) {
#pragma unroll
        for (int j = 0; j < 4; j++) {
            wmma::store_matrix_sync(wbuf, acc[i][j], 16, wmma::mem_row_major);
            __syncwarp();
            int m = m0 + wm * 32 + i * 16 + lr;
            int n = wn * 64 + j * 16 + lc;
            __half2 h[4];
#pragma unroll
            for (int e = 0; e < 4; e++)
                h[e] = __floats2half2_rn(wbuf[lr * 16 + lc + e * 2],
                                         wbuf[lr * 16 + lc + e * 2 + 1]);
            *(uint4*)&tmph[(size_t)m * 256 + n] = *(uint4*)h;
            __syncwarp();
        }
    }
}

// ---------------------------------------------------------------------------
// Stage 2: fp16 wmma GEMM (unchanged): BM=128, BN=128, KT=32; 256 threads;
// 3-stage cp.async; 2 CTAs/SM; fp16 staged output.
// ---------------------------------------------------------------------------
__global__ __launch_bounds__(256, 2)
void h16_gemm2(const __half* __restrict__ A, int lda,
               const __half* __restrict__ B0, const __half* __restrict__ B1,
               int ldb, int nsplit, int K,
               __half* __restrict__ Ch, int ldc) {
    constexpr int ALD = 40;
    constexpr int BLD = 136;
    constexpr int ASTG = 128 * ALD;
    constexpr int BSTG = 32 * BLD;

    extern __shared__ __align__(16) __half smh[];
    __half* As = smh;
    __half* Bs = smh + 3 * ASTG;

    const int tid  = threadIdx.x;
    const int warp = tid >> 5;
    const int lane = tid & 31;
    const int wm = warp >> 1;
    const int wn = warp & 1;
    const int m0 = blockIdx.y * 128;
    const int n0 = blockIdx.x * 128;

    const __half* Bp = (n0 < nsplit) ? B0 : B1;
    const int bn0    = (n0 < nsplit) ? n0 : n0 - nsplit;
    const int aoff   = (n0 >= nsplit) ? R_ : 0;

    auto load_stage = [&](int s, int k0) {
#pragma unroll
        for (int i = 0; i < 2; i++) {
            int q = tid + i * 256;
            int ar = q >> 2, ac = (q & 3) * 8;
            cp_async16(&As[s * ASTG + ar * ALD + ac],
                       &A[(size_t)(m0 + ar) * lda + aoff + k0 + ac]);
        }
#pragma unroll
        for (int i = 0; i < 2; i++) {
            int q = tid + i * 256;
            int br = q >> 4, bc = (q & 15) * 8;
            cp_async16(&Bs[s * BSTG + br * BLD + bc],
                       &Bp[(size_t)(k0 + br) * ldb + bn0 + bc]);
        }
        cp_commit();
    };

    wmma::fragment<wmma::accumulator, 16, 16, 16, float> acc[2][4];
#pragma unroll
    for (int i = 0; i < 2; i++)
#pragma unroll
        for (int j = 0; j < 4; j++) wmma::fill_fragment(acc[i][j], 0.0f);

    const int nK = K / 32;
    load_stage(0, 0);
    if (nK > 1) load_stage(1, 32);

    for (int kt = 0; kt < nK; kt++) {
        const int s = kt % 3;
        if (kt + 2 < nK) { load_stage((kt + 2) % 3, (kt + 2) * 32); cp_wait<2>(); }
        else if (kt + 1 < nK) { cp_wait<1>(); }
        else { cp_wait<0>(); }
        __syncthreads();

#pragma unroll
        for (int ks = 0; ks < 2; ks++) {
            wmma::fragment<wmma::matrix_a, 16, 16, 16, __half, wmma::row_major> af[2];
            wmma::fragment<wmma::matrix_b, 16, 16, 16, __half, wmma::row_major> bf[4];
#pragma unroll
            for (int i = 0; i < 2; i++)
                wmma::load_matrix_sync(af[i], &As[s * ASTG + (wm * 32 + i * 16) * ALD + ks * 16], ALD);
#pragma unroll
            for (int j = 0; j < 4; j++)
                wmma::load_matrix_sync(bf[j], &Bs[s * BSTG + (ks * 16) * BLD + wn * 64 + j * 16], BLD);
#pragma unroll
            for (int i = 0; i < 2; i++)
#pragma unroll
                for (int j = 0; j < 4; j++)
                    wmma::mma_sync(acc[i][j], af[i], bf[j], acc[i][j]);
        }
        __syncthreads();
    }

    float* wbuf = (float*)smh + warp * 256;
    const int lr = lane >> 1;
    const int lc = (lane & 1) * 8;
#pragma unroll
    for (int i = 0; i < 2; i++) {
#pragma unroll
        for (int j = 0; j < 4; j++) {
            wmma::store_matrix_sync(wbuf, acc[i][j], 16, wmma::mem_row_major);
            __syncwarp();
            int m = m0 + wm * 32 + i * 16 + lr;
            int n = n0 + wn * 64 + j * 16 + lc;
            __half2 h[4];
#pragma unroll
            for (int e = 0; e < 4; e++)
                h[e] = __floats2half2_rn(wbuf[lr * 16 + lc + e * 2],
                                         wbuf[lr * 16 + lc + e * 2 + 1]);
            *(uint4*)&Ch[(size_t)m * ldc + n] = *(uint4*)h;
            __syncwarp();
        }
    }
}

// ---------------------------------------------------------------------------
// Chunk-parallel scan, 2 channels per thread (half2 loads / float2 stores).
// idx -> (b, chunk j, channel-pair hp); hp fastest for coalescing.
// ---------------------------------------------------------------------------
__global__ void scanA_kernel(const __half* __restrict__ bxby,
                             float* __restrict__ e1, float* __restrict__ e2) {
    int idx = blockIdx.x * blockDim.x + threadIdx.x;    // B*C*H/2
    int hp = idx & (H_ / 2 - 1);
    int j  = (idx >> 9) & (C_ - 1);
    int b  = idx >> 13;
    int h  = hp * 2;
    float g0 = d_g[h],     p0 = d_phi[h];
    float g1 = d_g[h + 1], p1 = d_phi[h + 1];
    float c1a = 0.f, c2a = 0.f, c1b = 0.f, c2b = 0.f;
    const __half2* base = (const __half2*)(bxby + (size_t)(b * T_ + j * L_) * (2 * H_)) + hp;
#pragma unroll 4
    for (int t = 0; t < L_; t++) {
        float2 bx = __half22float2(base[(size_t)t * H_]);
        float2 by = __half22float2(base[(size_t)t * H_ + H_ / 2]);
        float n1a = fmaf(g0, c1a, fmaf(-p0, c2a, bx.x));
        float n2a = fmaf(p0, c1a, fmaf(g0, c2a, by.x));
        float n1b = fmaf(g1, c1b, fmaf(-p1, c2b, bx.y));
        float n2b = fmaf(p1, c1b, fmaf(g1, c2b, by.y));
        c1a = n1a; c2a = n2a; c1b = n1b; c2b = n2b;
    }
    int eidx = (b * C_ + j) * H_ + h;
    *(float2*)&e1[eidx] = make_float2(c1a, c1b);
    *(float2*)&e2[eidx] = make_float2(c2a, c2b);
}

__global__ void combine_kernel(const float* __restrict__ e1,
                               const float* __restrict__ e2,
                               const float* __restrict__ hc1,
                               const float* __restrict__ hc2,
                               float* __restrict__ i1, float* __restrict__ i2) {
    int idx = blockIdx.x * blockDim.x + threadIdx.x;    // B*H
    int h = idx & (H_ - 1);
    int b = idx >> 10;
    float lr = d_g[h], li = d_phi[h];
#pragma unroll
    for (int s = 0; s < 7; s++) {          // lambda^128
        float nr = lr * lr - li * li;
        float ni = 2.0f * lr * li;
        lr = nr; li = ni;
    }
    float c1 = hc1[idx], c2 = hc2[idx];
#pragma unroll
    for (int j = 0; j < C_; j++) {
        int eidx = (b * C_ + j) * H_ + h;
        i1[eidx] = c1; i2[eidx] = c2;
        float n1 = lr * c1 - li * c2 + e1[eidx];
        float n2 = li * c1 + lr * c2 + e2[eidx];
        c1 = n1; c2 = n2;
    }
}

__global__ void scanB_kernel(const __half* __restrict__ bxby,
                             const float* __restrict__ i1,
                             const float* __restrict__ i2,
                             float* __restrict__ out) {
    int idx = blockIdx.x * blockDim.x + threadIdx.x;    // B*C*H/2
    int hp = idx & (H_ / 2 - 1);
    int j  = (idx >> 9) & (C_ - 1);
    int b  = idx >> 13;
    int h  = hp * 2;
    float g0 = d_g[h],     p0 = d_phi[h];
    float g1 = d_g[h + 1], p1 = d_phi[h + 1];
    int iidx = (b * C_ + j) * H_ + h;
    float2 c1v = *(const float2*)&i1[iidx];
    float2 c2v = *(const float2*)&i2[iidx];
    float c1a = c1v.x, c1b = c1v.y, c2a = c2v.x, c2b = c2v.y;
    const __half2* base = (const __half2*)(bxby + (size_t)(b * T_ + j * L_) * (2 * H_)) + hp;
    float* ybase = out + (size_t)(b * T_ + j * L_) * (2 * H_) + h;
#pragma unroll 4
    for (int t = 0; t < L_; t++) {
        float2 bx = __half22float2(base[(size_t)t * H_]);
        float2 by = __half22float2(base[(size_t)t * H_ + H_ / 2]);
        float n1a = fmaf(g0, c1a, fmaf(-p0, c2a, bx.x));
        float n2a = fmaf(p0, c1a, fmaf(g0, c2a, by.x));
        float n1b = fmaf(g1, c1b, fmaf(-p1, c2b, bx.y));
        float n2b = fmaf(p1, c1b, fmaf(g1, c2b, by.y));
        c1a = n1a; c2a = n2a; c1b = n1b; c2b = n2b;
        *(float2*)&ybase[(size_t)t * (2 * H_)]      = make_float2(c1a, c1b);
        *(float2*)&ybase[(size_t)t * (2 * H_) + H_] = make_float2(c2a, c2b);
    }
    if (j == C_ - 1) {
        size_t y_elems = (size_t)B_ * T_ * (2 * H_);
        *(float2*)&out[y_elems + b * H_ + h]            = make_float2(c1a, c1b);
        *(float2*)&out[y_elems + B_ * H_ + b * H_ + h]  = make_float2(c2a, c2b);
    }
}

// ---------------------------------------------------------------------------
// Launch
// ---------------------------------------------------------------------------
extern "C" void kernel_launch(void* const* d_in, const int* in_sizes, int n_in,
                              void* d_out, int out_size) {
    const float* x         = (const float*)d_in[0];
    const float* nu_log    = (const float*)d_in[1];
    const float* theta_log = (const float*)d_in[2];
    const float* U1        = (const float*)d_in[3];
    const float* U2        = (const float*)d_in[4];
    const float* V1        = (const float*)d_in[5];
    const float* V2        = (const float*)d_in[6];
    const float* hc1       = (const float*)d_in[7];
    const float* hc2       = (const float*)d_in[8];
    float* out = (float*)d_out;

    __half *u1h, *u2h, *v1h, *v2h, *tmph, *bxbyh;
    float *e1, *e2, *i1, *i2;
    cudaGetSymbolAddress((void**)&u1h,   d_u1h);
    cudaGetSymbolAddress((void**)&u2h,   d_u2h);
    cudaGetSymbolAddress((void**)&v1h,   d_v1h);
    cudaGetSymbolAddress((void**)&v2h,   d_v2h);
    cudaGetSymbolAddress((void**)&tmph,  d_tmph);
    cudaGetSymbolAddress((void**)&bxbyh, d_bxbyh);
    cudaGetSymbolAddress((void**)&e1, d_e1);
    cudaGetSymbolAddress((void**)&e2, d_e2);
    cudaGetSymbolAddress((void**)&i1, d_i1);
    cudaGetSymbolAddress((void**)&i2, d_i2);

    const int smem1 = 2 * (128 * 40 + 32 * 264) * 2;   // 54272 B
    const int smem2 = 3 * (128 * 40 + 32 * 136) * 2;   // 56832 B
    cudaFuncSetAttribute(gemm1_fused, cudaFuncAttributeMaxDynamicSharedMemorySize, smem1);
    cudaFuncSetAttribute(h16_gemm2, cudaFuncAttributeMaxDynamicSharedMemorySize, smem2);

    prep_kernel<<<(R_ * H_ + 255) / 256, 256>>>(nu_log, theta_log, U1, U2, V1, V2);

    // Stage 1 (fused x conversion): tmph = fp16(x) @ [U1|U2], x read once
    gemm1_fused<<<M_ / 128, 512, smem1>>>(x, u1h, u2h, tmph);

    // Stage 2: bxby[:,0:H]=tmp1@(V1*g), bxby[:,H:2H]=tmp2@(V2*g)  (K=128)
    h16_gemm2<<<dim3(2 * H_ / 128, M_ / 128), 256, smem2>>>(
        tmph, 2 * R_, v1h, v2h, H_, H_, R_, bxbyh, 2 * H_);

    // Stage 3: chunk-parallel scan (2 channels/thread)
    scanA_kernel<<<(B_ * C_ * H_ / 2) / 256, 256>>>(bxbyh, e1, e2);
    combine_kernel<<<(B_ * H_) / 256, 256>>>(e1, e2, hc1, hc2, i1, i2);
    scanB_kernel<<<(B_ * C_ * H_ / 2) / 256, 256>>>(bxbyh, i1, i2, out);
}

// round 16
// speedup vs baseline: 1.0589x; 1.0589x over previous
#include <cuda_runtime.h>
#include <cuda_fp16.h>
#include <cstdint>
#include <mma.h>

using namespace nvcuda;

// Problem constants
#define B_  8
#define T_  2048
#define D_  1024
#define H_  1024
#define R_  128
#define M_  (B_*T_)      // 16384 rows
#define C_  64           // scan chunks
#define L_  32           // chunk length (T_/C_)

// ---------------------------------------------------------------------------
// Scratch (device globals: allocation APIs are forbidden)
// ---------------------------------------------------------------------------
__device__ __half d_u1h[D_ * R_], d_u2h[D_ * R_];
__device__ __half d_v1h[R_ * H_], d_v2h[R_ * H_];   // pre-scaled by gamma
__device__ __half d_tmph[(size_t)M_ * 2 * R_];      // 8 MB: x@U1 | x@U2 (fp16)
__device__ __half d_bxbyh[(size_t)M_ * 2 * H_];     // 64 MB (fp16)
__device__ float d_e1[B_ * C_ * H_], d_e2[B_ * C_ * H_];
__device__ float d_i1[B_ * C_ * H_], d_i2[B_ * C_ * H_];
__device__ float d_g[H_], d_phi[H_];

// ---------------------------------------------------------------------------
// Prep: decay params + U conv + V conv (gamma recomputed per V-thread).
// ---------------------------------------------------------------------------
__global__ void prep_kernel(const float* __restrict__ nu_log,
                            const float* __restrict__ theta_log,
                            const float* __restrict__ U1,
                            const float* __restrict__ U2,
                            const float* __restrict__ V1,
                            const float* __restrict__ V2) {
    int i = blockIdx.x * blockDim.x + threadIdx.x;
    if (i < H_) {
        float r = expf(-expf(nu_log[i]));
        float th = expf(theta_log[i]);
        d_g[i]   = r * cosf(th);
        d_phi[i] = r * sinf(th);
    }
    if (i < D_ * R_) {
        d_u1h[i] = __float2half_rn(U1[i]);
        d_u2h[i] = __float2half_rn(U2[i]);
    }
    if (i < R_ * H_) {
        int h = i % H_;
        float r = expf(-expf(nu_log[h]));
        float gm = sqrtf(fmaxf(1.0f - r * r, 0.0f));
        d_v1h[i] = __float2half_rn(V1[i] * gm);
        d_v2h[i] = __float2half_rn(V2[i] * gm);
    }
}

// cp.async helpers
__device__ __forceinline__ void cp_async16(void* dst, const void* src) {
    unsigned s = (unsigned)__cvta_generic_to_shared(dst);
    asm volatile("cp.async.ca.shared.global [%0], [%1], 16;" :: "r"(s), "l"(src));
}
__device__ __forceinline__ void cp_commit() { asm volatile("cp.async.commit_group;"); }
template <int N>
__device__ __forceinline__ void cp_wait() { asm volatile("cp.async.wait_group %0;" :: "n"(N)); }

// ---------------------------------------------------------------------------
// Stage 1 (fused x conversion): tmph[M,256] = fp16(x) @ [U1|U2]
// BM=128, BN=256 (x read ONCE), 512 threads = 16 warps (4m x 4n; 32x64/warp),
// KT=32, double-buffered: A prefetched fp32 -> converted -> STS; B cp.async.
// ---------------------------------------------------------------------------
__global__ __launch_bounds__(512, 1)
void gemm1_fused(const float* __restrict__ x,
                 const __half* __restrict__ u1h, const __half* __restrict__ u2h,
                 __half* __restrict__ tmph) {
    constexpr int ALD = 40;
    constexpr int BLD = 264;
    constexpr int ASTG = 128 * ALD;
    constexpr int BSTG = 32 * BLD;

    extern __shared__ __align__(16) __half smh[];
    __half* As = smh;                  // [2][128][40]
    __half* Bs = smh + 2 * ASTG;       // [2][32][264]

    const int tid  = threadIdx.x;
    const int warp = tid >> 5;
    const int lane = tid & 31;
    const int wm = warp >> 2;
    const int wn = warp & 3;
    const int m0 = blockIdx.x * 128;

    const int a_row = tid >> 2, a_col = (tid & 3) * 8;
    const int b_row = tid >> 4, b_col = (tid & 15) * 16;
    const __half* bsrc = (b_col < R_) ? &u1h[b_col] : &u2h[b_col - R_];

    float4 pa[2];
    auto prefA = [&](int k0) {
        const float* ap = &x[(size_t)(m0 + a_row) * D_ + k0 + a_col];
        pa[0] = *(const float4*)ap;
        pa[1] = *(const float4*)(ap + 4);
    };
    auto stageA = [&](int s) {
        __half2 h[4];
        h[0] = __floats2half2_rn(pa[0].x, pa[0].y);
        h[1] = __floats2half2_rn(pa[0].z, pa[0].w);
        h[2] = __floats2half2_rn(pa[1].x, pa[1].y);
        h[3] = __floats2half2_rn(pa[1].z, pa[1].w);
        *(uint4*)&As[s * ASTG + a_row * ALD + a_col] = *(uint4*)h;
    };
    auto cpB = [&](int s, int k0) {
        const __half* bp = bsrc + (size_t)(k0 + b_row) * R_;
        cp_async16(&Bs[s * BSTG + b_row * BLD + b_col],     bp);
        cp_async16(&Bs[s * BSTG + b_row * BLD + b_col + 8], bp + 8);
        cp_commit();
    };

    wmma::fragment<wmma::accumulator, 16, 16, 16, float> acc[2][4];
#pragma unroll
    for (int i = 0; i < 2; i++)
#pragma unroll
        for (int j = 0; j < 4; j++) wmma::fill_fragment(acc[i][j], 0.0f);

    const int nK = D_ / 32;
    prefA(0);
    cpB(0, 0);

    for (int kt = 0; kt < nK; kt++) {
        const int s = kt & 1;
        stageA(s);
        if (kt + 1 < nK) {
            prefA((kt + 1) * 32);
            cpB(1 - s, (kt + 1) * 32);
            cp_wait<1>();
        } else {
            cp_wait<0>();
        }
        __syncthreads();

#pragma unroll
        for (int ks = 0; ks < 2; ks++) {
            wmma::fragment<wmma::matrix_a, 16, 16, 16, __half, wmma::row_major> af[2];
            wmma::fragment<wmma::matrix_b, 16, 16, 16, __half, wmma::row_major> bf[4];
#pragma unroll
            for (int i = 0; i < 2; i++)
                wmma::load_matrix_sync(af[i], &As[s * ASTG + (wm * 32 + i * 16) * ALD + ks * 16], ALD);
#pragma unroll
            for (int j = 0; j < 4; j++)
                wmma::load_matrix_sync(bf[j], &Bs[s * BSTG + (ks * 16) * BLD + wn * 64 + j * 16], BLD);
#pragma unroll
            for (int i = 0; i < 2; i++)
#pragma unroll
                for (int j = 0; j < 4; j++)
                    wmma::mma_sync(acc[i][j], af[i], bf[j], acc[i][j]);
        }
        __syncthreads();
    }

    float* wbuf = (float*)smh + warp * 256;
    const int lr = lane >> 1;
    const int lc = (lane & 1) * 8;
#pragma unroll
    for (int i = 0; i < 2; i++) {
#pragma unroll
        for (int j = 0; j < 4; j++) {
            wmma::store_matrix_sync(wbuf, acc[i][j], 16, wmma::mem_row_major);
            __syncwarp();
            int m = m0 + wm * 32 + i * 16 + lr;
            int n = wn * 64 + j * 16 + lc;
            __half2 h[4];
#pragma unroll
            for (int e = 0; e < 4; e++)
                h[e] = __floats2half2_rn(wbuf[lr * 16 + lc + e * 2],
                                         wbuf[lr * 16 + lc + e * 2 + 1]);
            *(uint4*)&tmph[(size_t)m * 256 + n] = *(uint4*)h;
            __syncwarp();
        }
    }
}

// ---------------------------------------------------------------------------
// Stage 2: fp16 wmma GEMM: BM=128, BN=128, KT=32; 256 threads;
// 3-stage cp.async; 2 CTAs/SM; fp16 staged output.
// ---------------------------------------------------------------------------
__global__ __launch_bounds__(256, 2)
void h16_gemm2(const __half* __restrict__ A, int lda,
               const __half* __restrict__ B0, const __half* __restrict__ B1,
               int ldb, int nsplit, int K,
               __half* __restrict__ Ch, int ldc) {
    constexpr int ALD = 40;
    constexpr int BLD = 136;
    constexpr int ASTG = 128 * ALD;
    constexpr int BSTG = 32 * BLD;

    extern __shared__ __align__(16) __half smh[];
    __half* As = smh;
    __half* Bs = smh + 3 * ASTG;

    const int tid  = threadIdx.x;
    const int warp = tid >> 5;
    const int lane = tid & 31;
    const int wm = warp >> 1;
    const int wn = warp & 1;
    const int m0 = blockIdx.y * 128;
    const int n0 = blockIdx.x * 128;

    const __half* Bp = (n0 < nsplit) ? B0 : B1;
    const int bn0    = (n0 < nsplit) ? n0 : n0 - nsplit;
    const int aoff   = (n0 >= nsplit) ? R_ : 0;

    auto load_stage = [&](int s, int k0) {
#pragma unroll
        for (int i = 0; i < 2; i++) {
            int q = tid + i * 256;
            int ar = q >> 2, ac = (q & 3) * 8;
            cp_async16(&As[s * ASTG + ar * ALD + ac],
                       &A[(size_t)(m0 + ar) * lda + aoff + k0 + ac]);
        }
#pragma unroll
        for (int i = 0; i < 2; i++) {
            int q = tid + i * 256;
            int br = q >> 4, bc = (q & 15) * 8;
            cp_async16(&Bs[s * BSTG + br * BLD + bc],
                       &Bp[(size_t)(k0 + br) * ldb + bn0 + bc]);
        }
        cp_commit();
    };

    wmma::fragment<wmma::accumulator, 16, 16, 16, float> acc[2][4];
#pragma unroll
    for (int i = 0; i < 2; i++)
#pragma unroll
        for (int j = 0; j < 4; j++) wmma::fill_fragment(acc[i][j], 0.0f);

    const int nK = K / 32;
    load_stage(0, 0);
    if (nK > 1) load_stage(1, 32);

    for (int kt = 0; kt < nK; kt++) {
        const int s = kt % 3;
        if (kt + 2 < nK) { load_stage((kt + 2) % 3, (kt + 2) * 32); cp_wait<2>(); }
        else if (kt + 1 < nK) { cp_wait<1>(); }
        else { cp_wait<0>(); }
        __syncthreads();

#pragma unroll
        for (int ks = 0; ks < 2; ks++) {
            wmma::fragment<wmma::matrix_a, 16, 16, 16, __half, wmma::row_major> af[2];
            wmma::fragment<wmma::matrix_b, 16, 16, 16, __half, wmma::row_major> bf[4];
#pragma unroll
            for (int i = 0; i < 2; i++)
                wmma::load_matrix_sync(af[i], &As[s * ASTG + (wm * 32 + i * 16) * ALD + ks * 16], ALD);
#pragma unroll
            for (int j = 0; j < 4; j++)
                wmma::load_matrix_sync(bf[j], &Bs[s * BSTG + (ks * 16) * BLD + wn * 64 + j * 16], BLD);
#pragma unroll
            for (int i = 0; i < 2; i++)
#pragma unroll
                for (int j = 0; j < 4; j++)
                    wmma::mma_sync(acc[i][j], af[i], bf[j], acc[i][j]);
        }
        __syncthreads();
    }

    float* wbuf = (float*)smh + warp * 256;
    const int lr = lane >> 1;
    const int lc = (lane & 1) * 8;
#pragma unroll
    for (int i = 0; i < 2; i++) {
#pragma unroll
        for (int j = 0; j < 4; j++) {
            wmma::store_matrix_sync(wbuf, acc[i][j], 16, wmma::mem_row_major);
            __syncwarp();
            int m = m0 + wm * 32 + i * 16 + lr;
            int n = n0 + wn * 64 + j * 16 + lc;
            __half2 h[4];
#pragma unroll
            for (int e = 0; e < 4; e++)
                h[e] = __floats2half2_rn(wbuf[lr * 16 + lc + e * 2],
                                         wbuf[lr * 16 + lc + e * 2 + 1]);
            *(uint4*)&Ch[(size_t)m * ldc + n] = *(uint4*)h;
            __syncwarp();
        }
    }
}

// ---------------------------------------------------------------------------
// Chunk-parallel scan: 1 channel/thread, C_=64 chunks for full occupancy.
// idx -> (b, chunk j, h); h fastest for coalescing.
// ---------------------------------------------------------------------------
__global__ void scanA_kernel(const __half* __restrict__ bxby,
                             float* __restrict__ e1, float* __restrict__ e2) {
    int idx = blockIdx.x * blockDim.x + threadIdx.x;    // B*C*H
    int h = idx & (H_ - 1);
    int j = (idx >> 10) & (C_ - 1);
    int b = idx >> 16;
    float gg = d_g[h], pp = d_phi[h];
    float c1 = 0.f, c2 = 0.f;
    const __half* base = bxby + ((size_t)(b * T_ + j * L_)) * (2 * H_) + h;
#pragma unroll 4
    for (int t = 0; t < L_; t++) {
        float bx = __half2float(base[(size_t)t * (2 * H_)]);
        float by = __half2float(base[(size_t)t * (2 * H_) + H_]);
        float n1 = fmaf(gg, c1, fmaf(-pp, c2, bx));
        float n2 = fmaf(pp, c1, fmaf(gg, c2, by));
        c1 = n1; c2 = n2;
    }
    e1[idx] = c1; e2[idx] = c2;
}

__global__ void combine_kernel(const float* __restrict__ e1,
                               const float* __restrict__ e2,
                               const float* __restrict__ hc1,
                               const float* __restrict__ hc2,
                               float* __restrict__ i1, float* __restrict__ i2) {
    int idx = blockIdx.x * blockDim.x + threadIdx.x;    // B*H
    int h = idx & (H_ - 1);
    int b = idx >> 10;
    float lr = d_g[h], li = d_phi[h];
#pragma unroll
    for (int s = 0; s < 5; s++) {          // lambda^32 (L=32=2^5)
        float nr = lr * lr - li * li;
        float ni = 2.0f * lr * li;
        lr = nr; li = ni;
    }
    float c1 = hc1[idx], c2 = hc2[idx];
#pragma unroll
    for (int j = 0; j < C_; j++) {
        int eidx = (b * C_ + j) * H_ + h;
        i1[eidx] = c1; i2[eidx] = c2;
        float n1 = lr * c1 - li * c2 + e1[eidx];
        float n2 = li * c1 + lr * c2 + e2[eidx];
        c1 = n1; c2 = n2;
    }
}

__global__ void scanB_kernel(const __half* __restrict__ bxby,
                             const float* __restrict__ i1,
                             const float* __restrict__ i2,
                             float* __restrict__ out) {
    int idx = blockIdx.x * blockDim.x + threadIdx.x;    // B*C*H
    int h = idx & (H_ - 1);
    int j = (idx >> 10) & (C_ - 1);
    int b = idx >> 16;
    float gg = d_g[h], pp = d_phi[h];
    float c1 = i1[idx], c2 = i2[idx];
    const __half* base = bxby + ((size_t)(b * T_ + j * L_)) * (2 * H_) + h;
    float*       ybase = out + ((size_t)(b * T_ + j * L_)) * (2 * H_) + h;
#pragma unroll 4
    for (int t = 0; t < L_; t++) {
        float bx = __half2float(base[(size_t)t * (2 * H_)]);
        float by = __half2float(base[(size_t)t * (2 * H_) + H_]);
        float n1 = fmaf(gg, c1, fmaf(-pp, c2, bx));
        float n2 = fmaf(pp, c1, fmaf(gg, c2, by));
        c1 = n1; c2 = n2;
        ybase[(size_t)t * (2 * H_)]      = c1;
        ybase[(size_t)t * (2 * H_) + H_] = c2;
    }
    if (j == C_ - 1) {
        size_t y_elems = (size_t)B_ * T_ * (2 * H_);
        out[y_elems + b * H_ + h]            = c1;
        out[y_elems + B_ * H_ + b * H_ + h]  = c2;
    }
}

// ---------------------------------------------------------------------------
// Launch
// ---------------------------------------------------------------------------
extern "C" void kernel_launch(void* const* d_in, const int* in_sizes, int n_in,
                              void* d_out, int out_size) {
    const float* x         = (const float*)d_in[0];
    const float* nu_log    = (const float*)d_in[1];
    const float* theta_log = (const float*)d_in[2];
    const float* U1        = (const float*)d_in[3];
    const float* U2        = (const float*)d_in[4];
    const float* V1        = (const float*)d_in[5];
    const float* V2        = (const float*)d_in[6];
    const float* hc1       = (const float*)d_in[7];
    const float* hc2       = (const float*)d_in[8];
    float* out = (float*)d_out;

    __half *u1h, *u2h, *v1h, *v2h, *tmph, *bxbyh;
    float *e1, *e2, *i1, *i2;
    cudaGetSymbolAddress((void**)&u1h,   d_u1h);
    cudaGetSymbolAddress((void**)&u2h,   d_u2h);
    cudaGetSymbolAddress((void**)&v1h,   d_v1h);
    cudaGetSymbolAddress((void**)&v2h,   d_v2h);
    cudaGetSymbolAddress((void**)&tmph,  d_tmph);
    cudaGetSymbolAddress((void**)&bxbyh, d_bxbyh);
    cudaGetSymbolAddress((void**)&e1, d_e1);
    cudaGetSymbolAddress((void**)&e2, d_e2);
    cudaGetSymbolAddress((void**)&i1, d_i1);
    cudaGetSymbolAddress((void**)&i2, d_i2);

    const int smem1 = 2 * (128 * 40 + 32 * 264) * 2;   // 54272 B
    const int smem2 = 3 * (128 * 40 + 32 * 136) * 2;   // 56832 B
    cudaFuncSetAttribute(gemm1_fused, cudaFuncAttributeMaxDynamicSharedMemorySize, smem1);
    cudaFuncSetAttribute(h16_gemm2, cudaFuncAttributeMaxDynamicSharedMemorySize, smem2);

    prep_kernel<<<(R_ * H_ + 255) / 256, 256>>>(nu_log, theta_log, U1, U2, V1, V2);

    // Stage 1 (fused x conversion): tmph = fp16(x) @ [U1|U2], x read once
    gemm1_fused<<<M_ / 128, 512, smem1>>>(x, u1h, u2h, tmph);

    // Stage 2: bxby[:,0:H]=tmp1@(V1*g), bxby[:,H:2H]=tmp2@(V2*g)  (K=128)
    h16_gemm2<<<dim3(2 * H_ / 128, M_ / 128), 256, smem2>>>(
        tmph, 2 * R_, v1h, v2h, H_, H_, R_, bxbyh, 2 * H_);

    // Stage 3: chunk-parallel scan (C=64 chunks -> full occupancy)
    scanA_kernel<<<(B_ * C_ * H_) / 256, 256>>>(bxbyh, e1, e2);
    combine_kernel<<<(B_ * H_) / 256, 256>>>(e1, e2, hc1, hc2, i1, i2);
    scanB_kernel<<<(B_ * C_ * H_) / 256, 256>>>(bxbyh, i1, i2, out);
}